// round 13
// baseline (speedup 1.0000x reference)
#include <cuda_runtime.h>
#include <math.h>

#define B 32
#define D 64
#define H 192
#define W 128
#define K 64
#define CPB 4                   // CTAs per batch = cluster size
#define GRID (B * CPB)          // 128 CTAs, single wave
#define THREADS 512
#define KPC (K / CPB)           // 16 keypoints / i-rows per CTA
#define ROWPAD 68               // row stride (words): 16B-aligned

#define QSCALE 1048576.0f       // 2^20 fixed-point scale
#define CNT_ONE (1ULL << 44)
#define QMASK   ((1ULL << 44) - 1)
#define EXPO_C  (1.4426950408889634f / (float)D)   // log2(e)/D

__device__ unsigned long long g_acc = 0ULL;   // packed {counter, fixed-point sum}

// ---- PTX helpers ----
__device__ __forceinline__ unsigned long long ffma2(unsigned long long a,
                                                    unsigned long long b,
                                                    unsigned long long c)
{
    unsigned long long d;
    asm("fma.rn.f32x2 %0, %1, %2, %3;" : "=l"(d) : "l"(a), "l"(b), "l"(c));
    return d;
}
__device__ __forceinline__ float2 unpack2(unsigned long long v)
{
    float x, y;
    asm("mov.b64 {%0, %1}, %2;" : "=f"(x), "=f"(y) : "l"(v));
    return make_float2(x, y);
}
__device__ __forceinline__ unsigned long long pack2(float x, float y)
{
    unsigned long long v;
    asm("mov.b64 %0, {%1, %2};" : "=l"(v) : "f"(x), "f"(y));
    return v;
}
__device__ __forceinline__ unsigned smem_u32(const void* p)
{
    unsigned a;
    asm("{ .reg .u64 t; cvta.to.shared.u64 t, %1; cvt.u32.u64 %0, t; }"
        : "=r"(a) : "l"(p));
    return a;
}
__device__ __forceinline__ unsigned mapa_u32(unsigned addr, unsigned rank)
{
    unsigned r;
    asm("mapa.shared::cluster.u32 %0, %1, %2;" : "=r"(r) : "r"(addr), "r"(rank));
    return r;
}
__device__ __forceinline__ void st_cluster_b64(unsigned addr, unsigned long long v)
{
    asm volatile("st.shared::cluster.b64 [%0], %1;" :: "r"(addr), "l"(v) : "memory");
}
__device__ __forceinline__ unsigned ctarank()
{
    unsigned r;
    asm("mov.u32 %0, %%cluster_ctarank;" : "=r"(r));
    return r;
}

__global__ __launch_bounds__(THREADS, 1) __cluster_dims__(CPB, 1, 1)
void tagloss_fused_kernel(const float* __restrict__ ebd,
                          const float* __restrict__ kpts,
                          const int*   __restrict__ tags,
                          float*       __restrict__ out)
{
    const int cta   = blockIdx.x;
    const int b     = cta >> 2;
    const int chunk = (int)ctarank();
    const int tid   = threadIdx.x;

    __shared__ __align__(16) float erow[K][ROWPAD];  // 64 rows, filled by cluster
    __shared__ float swarp[THREADS / 32];

    // ---- FIRST: kpts load (head of the serial chain) ----
    const int kl   = tid >> 5;                       // 0..15 local keypoint
    const int lane = tid & 31;                       // d = 2*lane
    float2 rc = ((const float2*)kpts)[(size_t)b * K + chunk * KPC + kl];

    // ---- independent tags loads (issue behind kpts) ----
    const int j  = tid & 63;
    const int i0 = chunk * KPC + (tid >> 6);
    const int i1 = i0 + 8;
    const int tj  = tags[(size_t)b * K + j];
    const int ti0 = tags[(size_t)b * K + i0];
    const int ti1 = tags[(size_t)b * K + i1];

    const int r = (int)floorf(rc.x * (float)H);
    const int c = (int)floorf(rc.y * (float)W);

    const float* eb = ebd + (size_t)b * D * H * W + (size_t)r * W + c;
    float v0 = eb[(size_t)(2 * lane)     * (H * W)];
    float v1 = eb[(size_t)(2 * lane + 1) * (H * W)];
    unsigned long long vp = pack2(v0, v1);

    // ---- broadcast: local quarter via STS, 3 remote quarters via DSMEM ----
    {
        float* dst = &erow[chunk * KPC + kl][2 * lane];
        *(unsigned long long*)dst = vp;              // plain STS (own SMEM)
        unsigned vaddr = smem_u32(dst);
        #pragma unroll
        for (unsigned rk = 0; rk < CPB; rk++) {
            if (rk != (unsigned)chunk)
                st_cluster_b64(mapa_u32(vaddr, rk), vp);
        }
    }
    // cluster barrier: collective release/acquire for the DSMEM stores
    asm volatile("barrier.cluster.arrive.aligned;" ::: "memory");
    asm volatile("barrier.cluster.wait.aligned;"   ::: "memory");

    // ---- hoist own column j (packed f32x2) + own norm (register-local) ----
    unsigned long long ejp[D / 2];
    {
        const ulonglong2* myrow = (const ulonglong2*)erow[j];
        #pragma unroll
        for (int d4 = 0; d4 < D / 4; d4++) {
            ulonglong2 t = myrow[d4];
            ejp[2 * d4 + 0] = t.x;
            ejp[2 * d4 + 1] = t.y;
        }
    }
    float nj;
    {
        unsigned long long s01 = 0ull, s23 = 0ull;
        #pragma unroll
        for (int d4 = 0; d4 < D / 4; d4++) {
            s01 = ffma2(ejp[2 * d4 + 0], ejp[2 * d4 + 0], s01);
            s23 = ffma2(ejp[2 * d4 + 1], ejp[2 * d4 + 1], s23);
        }
        float2 a = unpack2(s01), bb = unpack2(s23);
        nj = (a.x + a.y) + (bb.x + bb.y);
    }

    // ---- pairwise loss: 2 i-rows per thread; i-norm computed inline ----
    float acc = 0.0f;
    #pragma unroll
    for (int ig = 0; ig < 2; ig++) {
        const int i  = ig ? i1 : i0;
        const int ti = ig ? ti1 : ti0;
        const ulonglong2* rowi = (const ulonglong2*)erow[i];   // warp-broadcast LDS.128
        unsigned long long s01 = 0ull, s23 = 0ull;             // dot(e_i, e_j)
        unsigned long long n01 = 0ull, n23 = 0ull;             // ||e_i||^2
        #pragma unroll
        for (int d4 = 0; d4 < D / 4; d4++) {
            ulonglong2 v = rowi[d4];
            s01 = ffma2(v.x, ejp[2 * d4 + 0], s01);
            s23 = ffma2(v.y, ejp[2 * d4 + 1], s23);
            n01 = ffma2(v.x, v.x, n01);
            n23 = ffma2(v.y, v.y, n23);
        }
        float2 a = unpack2(s01), bb = unpack2(s23);
        float s = (a.x + a.y) + (bb.x + bb.y);
        float2 na = unpack2(n01), nb = unpack2(n23);
        float ni = (na.x + na.y) + (nb.x + nb.y);

        // 2/(1+exp(t/D)): /D and log2e folded into one constant
        float t    = fmaf(-2.0f, s, ni + nj);
        float e    = exp2f(t * EXPO_C);
        float pred = __fdividef(2.0f, 1.0f + e);
        float ts   = (ti == tj) ? 1.0f : 0.0f;
        float dd   = pred - ts;
        acc = fmaf(dd, dd, acc);
    }

    // ---- CTA reduction: warp shuffle tree, then one warp over 16 leaders ----
    #pragma unroll
    for (int o = 16; o > 0; o >>= 1)
        acc += __shfl_down_sync(0xFFFFFFFFu, acc, o);
    if (lane == 0) swarp[tid >> 5] = acc;
    __syncthreads();

    if (tid < 32) {
        float v = (tid < THREADS / 32) ? swarp[tid] : 0.0f;
        #pragma unroll
        for (int o = 8; o > 0; o >>= 1)
            v += __shfl_down_sync(0xFFFFFFFFu, v, o);
        if (tid == 0) {
            unsigned long long q   = (unsigned long long)llrintf(v * QSCALE);
            unsigned long long val = q + CNT_ONE;
            unsigned long long old;
            asm volatile("atom.acq_rel.gpu.global.add.u64 %0, [%1], %2;"
                         : "=l"(old) : "l"(&g_acc), "l"(val) : "memory");
            if ((old >> 44) == GRID - 1) {
                unsigned long long total = (old + val) & QMASK;
                out[0] = (float)total * (1.0f / (QSCALE * (float)(K * K * B)));
                g_acc = 0ULL;             // reset for next graph replay
            }
        }
    }
}

extern "C" void kernel_launch(void* const* d_in, const int* in_sizes, int n_in,
                              void* d_out, int out_size)
{
    const float* ebd  = (const float*)d_in[0];   // [32,64,192,128] f32
    const float* kpts = (const float*)d_in[1];   // [32,64,2] f32
    const int*   tags = (const int*)d_in[2];     // [32,64] i32
    float* out = (float*)d_out;

    tagloss_fused_kernel<<<GRID, THREADS>>>(ebd, kpts, tags, out);
}

// round 14
// speedup vs baseline: 1.0257x; 1.0257x over previous
#include <cuda_runtime.h>
#include <math.h>

#define B 32
#define D 64
#define H 192
#define W 128
#define K 64
#define CPB 4                   // CTAs per batch = cluster size
#define GRID (B * CPB)          // 128 CTAs, single wave
#define THREADS 512
#define KPC (K / CPB)           // 16 keypoints / i-rows per CTA
#define ROWPAD 68               // row stride (words): 16B-aligned

#define QSCALE 1048576.0f       // 2^20 fixed-point scale
#define CNT_ONE (1ULL << 44)
#define QMASK   ((1ULL << 44) - 1)
#define EXPO_C  (1.4426950408889634f / (float)D)   // log2(e)/D

__device__ unsigned long long g_acc = 0ULL;   // packed {counter, fixed-point sum}

// ---- PTX helpers ----
__device__ __forceinline__ unsigned long long ffma2(unsigned long long a,
                                                    unsigned long long b,
                                                    unsigned long long c)
{
    unsigned long long d;
    asm("fma.rn.f32x2 %0, %1, %2, %3;" : "=l"(d) : "l"(a), "l"(b), "l"(c));
    return d;
}
__device__ __forceinline__ float2 unpack2(unsigned long long v)
{
    float x, y;
    asm("mov.b64 {%0, %1}, %2;" : "=f"(x), "=f"(y) : "l"(v));
    return make_float2(x, y);
}
__device__ __forceinline__ unsigned long long pack2(float x, float y)
{
    unsigned long long v;
    asm("mov.b64 %0, {%1, %2};" : "=l"(v) : "f"(x), "f"(y));
    return v;
}
__device__ __forceinline__ unsigned smem_u32(const void* p)
{
    unsigned a;
    asm("{ .reg .u64 t; cvta.to.shared.u64 t, %1; cvt.u32.u64 %0, t; }"
        : "=r"(a) : "l"(p));
    return a;
}
__device__ __forceinline__ unsigned mapa_u32(unsigned addr, unsigned rank)
{
    unsigned r;
    asm("mapa.shared::cluster.u32 %0, %1, %2;" : "=r"(r) : "r"(addr), "r"(rank));
    return r;
}
__device__ __forceinline__ void st_cluster_b64(unsigned addr, unsigned long long v)
{
    asm volatile("st.shared::cluster.b64 [%0], %1;" :: "r"(addr), "l"(v) : "memory");
}
__device__ __forceinline__ unsigned ctarank()
{
    unsigned r;
    asm("mov.u32 %0, %%cluster_ctarank;" : "=r"(r));
    return r;
}

__global__ __launch_bounds__(THREADS, 1) __cluster_dims__(CPB, 1, 1)
void tagloss_fused_kernel(const float* __restrict__ ebd,
                          const float* __restrict__ kpts,
                          const int*   __restrict__ tags,
                          float*       __restrict__ out)
{
    const int cta   = blockIdx.x;
    const int b     = cta >> 2;
    const int chunk = (int)ctarank();
    const int tid   = threadIdx.x;

    __shared__ __align__(16) float erow[K][ROWPAD];  // 64 rows, filled by cluster
    __shared__ float swarp[THREADS / 32];

    // ---- FIRST: kpts load (head of the serial chain) ----
    const int kl   = tid >> 5;                       // 0..15 local keypoint
    const int lane = tid & 31;                       // d = 2*lane
    float2 rc = ((const float2*)kpts)[b * K + chunk * KPC + kl];

    // ---- independent tags loads (issue behind kpts) ----
    const int j  = tid & 63;
    const int i0 = chunk * KPC + (tid >> 6);
    const int i1 = i0 + 8;
    const int tj  = tags[b * K + j];
    const int ti0 = tags[b * K + i0];
    const int ti1 = tags[b * K + i1];
    const float ts0 = (ti0 == tj) ? 1.0f : 0.0f;     // off the pair-loop chain
    const float ts1 = (ti1 == tj) ? 1.0f : 0.0f;

    // ---- index math: F2I.RD (inputs non-negative), 32-bit offsets ----
    const int r = __float2int_rd(rc.x * (float)H);
    const int c = __float2int_rd(rc.y * (float)W);

    // all offsets < 2^26: keep address math in 32-bit
    const int base = b * (D * H * W) + r * W + c;
    const float* e0 = ebd + (base + (2 * lane)     * (H * W));
    const float* e1 = ebd + (base + (2 * lane + 1) * (H * W));
    float v0 = *e0;
    float v1 = *e1;
    unsigned long long vp = pack2(v0, v1);

    // ---- broadcast: local quarter via STS, 3 remote quarters via DSMEM ----
    {
        float* dst = &erow[chunk * KPC + kl][2 * lane];
        *(unsigned long long*)dst = vp;              // plain STS (own SMEM)
        unsigned vaddr = smem_u32(dst);
        #pragma unroll
        for (unsigned rk = 0; rk < CPB; rk++) {
            if (rk != (unsigned)chunk)
                st_cluster_b64(mapa_u32(vaddr, rk), vp);
        }
    }
    // cluster barrier: collective release/acquire for the DSMEM stores
    asm volatile("barrier.cluster.arrive.aligned;" ::: "memory");
    asm volatile("barrier.cluster.wait.aligned;"   ::: "memory");

    // ---- hoist own column j (packed f32x2) + own norm (register-local) ----
    unsigned long long ejp[D / 2];
    {
        const ulonglong2* myrow = (const ulonglong2*)erow[j];
        #pragma unroll
        for (int d4 = 0; d4 < D / 4; d4++) {
            ulonglong2 t = myrow[d4];
            ejp[2 * d4 + 0] = t.x;
            ejp[2 * d4 + 1] = t.y;
        }
    }
    float nj;
    {
        unsigned long long s01 = 0ull, s23 = 0ull;
        #pragma unroll
        for (int d4 = 0; d4 < D / 4; d4++) {
            s01 = ffma2(ejp[2 * d4 + 0], ejp[2 * d4 + 0], s01);
            s23 = ffma2(ejp[2 * d4 + 1], ejp[2 * d4 + 1], s23);
        }
        float2 a = unpack2(s01), bb = unpack2(s23);
        nj = (a.x + a.y) + (bb.x + bb.y);
    }

    // ---- pairwise loss: 2 i-rows per thread; i-norm computed inline ----
    float acc = 0.0f;
    #pragma unroll
    for (int ig = 0; ig < 2; ig++) {
        const int   i  = ig ? i1 : i0;
        const float ts = ig ? ts1 : ts0;
        const ulonglong2* rowi = (const ulonglong2*)erow[i];   // warp-broadcast LDS.128
        unsigned long long s01 = 0ull, s23 = 0ull;             // dot(e_i, e_j)
        unsigned long long n01 = 0ull, n23 = 0ull;             // ||e_i||^2
        #pragma unroll
        for (int d4 = 0; d4 < D / 4; d4++) {
            ulonglong2 v = rowi[d4];
            s01 = ffma2(v.x, ejp[2 * d4 + 0], s01);
            s23 = ffma2(v.y, ejp[2 * d4 + 1], s23);
            n01 = ffma2(v.x, v.x, n01);
            n23 = ffma2(v.y, v.y, n23);
        }
        float2 a = unpack2(s01), bb = unpack2(s23);
        float s = (a.x + a.y) + (bb.x + bb.y);
        float2 na = unpack2(n01), nb = unpack2(n23);
        float ni = (na.x + na.y) + (nb.x + nb.y);

        // 2/(1+exp(t/D)): /D and log2e folded into one constant
        float t    = fmaf(-2.0f, s, ni + nj);
        float e    = exp2f(t * EXPO_C);
        float pred = __fdividef(2.0f, 1.0f + e);
        float dd   = pred - ts;
        acc = fmaf(dd, dd, acc);
    }

    // ---- CTA reduction: warp shuffle tree, then one warp over 16 leaders ----
    #pragma unroll
    for (int o = 16; o > 0; o >>= 1)
        acc += __shfl_down_sync(0xFFFFFFFFu, acc, o);
    if (lane == 0) swarp[tid >> 5] = acc;
    __syncthreads();

    if (tid < 32) {
        float v = (tid < THREADS / 32) ? swarp[tid] : 0.0f;
        #pragma unroll
        for (int o = 8; o > 0; o >>= 1)
            v += __shfl_down_sync(0xFFFFFFFFu, v, o);
        if (tid == 0) {
            unsigned long long q   = (unsigned long long)llrintf(v * QSCALE);
            unsigned long long val = q + CNT_ONE;
            unsigned long long old;
            asm volatile("atom.acq_rel.gpu.global.add.u64 %0, [%1], %2;"
                         : "=l"(old) : "l"(&g_acc), "l"(val) : "memory");
            if ((old >> 44) == GRID - 1) {
                unsigned long long total = (old + val) & QMASK;
                out[0] = (float)total * (1.0f / (QSCALE * (float)(K * K * B)));
                g_acc = 0ULL;             // reset for next graph replay
            }
        }
    }
}

extern "C" void kernel_launch(void* const* d_in, const int* in_sizes, int n_in,
                              void* d_out, int out_size)
{
    const float* ebd  = (const float*)d_in[0];   // [32,64,192,128] f32
    const float* kpts = (const float*)d_in[1];   // [32,64,2] f32
    const int*   tags = (const int*)d_in[2];     // [32,64] i32
    float* out = (float*)d_out;

    tagloss_fused_kernel<<<GRID, THREADS>>>(ebd, kpts, tags, out);
}

// round 15
// speedup vs baseline: 1.0295x; 1.0037x over previous
#include <cuda_runtime.h>
#include <math.h>

#define B 32
#define D 64
#define H 192
#define W 128
#define K 64
#define CPB 4                   // CTAs per batch = cluster size
#define GRID (B * CPB)          // 128 CTAs, single wave
#define THREADS 512
#define KPC (K / CPB)           // 16 keypoints / i-rows per CTA
#define ROWPAD 68               // row stride (words): 16B-aligned

#define QSCALE 1048576.0f       // 2^20 fixed-point scale
#define CNT_ONE (1ULL << 44)
#define QMASK   ((1ULL << 44) - 1)
#define EXPO_C  (1.4426950408889634f / (float)D)   // log2(e)/D

__device__ unsigned long long g_acc = 0ULL;   // packed {counter, fixed-point sum}

// ---- PTX helpers ----
__device__ __forceinline__ unsigned long long ffma2(unsigned long long a,
                                                    unsigned long long b,
                                                    unsigned long long c)
{
    unsigned long long d;
    asm("fma.rn.f32x2 %0, %1, %2, %3;" : "=l"(d) : "l"(a), "l"(b), "l"(c));
    return d;
}
__device__ __forceinline__ float2 unpack2(unsigned long long v)
{
    float x, y;
    asm("mov.b64 {%0, %1}, %2;" : "=f"(x), "=f"(y) : "l"(v));
    return make_float2(x, y);
}
__device__ __forceinline__ unsigned long long pack2(float x, float y)
{
    unsigned long long v;
    asm("mov.b64 %0, {%1, %2};" : "=l"(v) : "f"(x), "f"(y));
    return v;
}
__device__ __forceinline__ unsigned smem_u32(const void* p)
{
    unsigned a;
    asm("{ .reg .u64 t; cvta.to.shared.u64 t, %1; cvt.u32.u64 %0, t; }"
        : "=r"(a) : "l"(p));
    return a;
}
__device__ __forceinline__ unsigned mapa_u32(unsigned addr, unsigned rank)
{
    unsigned r;
    asm("mapa.shared::cluster.u32 %0, %1, %2;" : "=r"(r) : "r"(addr), "r"(rank));
    return r;
}
__device__ __forceinline__ void st_cluster_b64(unsigned addr, unsigned long long v)
{
    asm volatile("st.shared::cluster.b64 [%0], %1;" :: "r"(addr), "l"(v) : "memory");
}
__device__ __forceinline__ unsigned ctarank()
{
    unsigned r;
    asm("mov.u32 %0, %%cluster_ctarank;" : "=r"(r));
    return r;
}

__global__ __launch_bounds__(THREADS, 1) __cluster_dims__(CPB, 1, 1)
void tagloss_fused_kernel(const float* __restrict__ ebd,
                          const float* __restrict__ kpts,
                          const int*   __restrict__ tags,
                          float*       __restrict__ out)
{
    const int cta   = blockIdx.x;
    const int b     = cta >> 2;
    const int chunk = (int)ctarank();
    const int tid   = threadIdx.x;

    __shared__ __align__(16) float erow[K][ROWPAD];  // 64 rows, filled by cluster
    __shared__ float swarp[THREADS / 32];

    // ---- FIRST: kpts load (head of the serial chain) ----
    const int kl   = tid >> 5;                       // 0..15 local keypoint
    const int lane = tid & 31;                       // d = 2*lane
    float2 rc = ((const float2*)kpts)[b * K + chunk * KPC + kl];

    // ---- independent tags loads (issue behind kpts) ----
    const int j  = tid & 63;
    const int i0 = chunk * KPC + (tid >> 6);
    const int i1 = i0 + 8;
    const int tj  = tags[b * K + j];
    const int ti0 = tags[b * K + i0];
    const int ti1 = tags[b * K + i1];
    const float ts0 = (ti0 == tj) ? 1.0f : 0.0f;     // off the pair-loop chain
    const float ts1 = (ti1 == tj) ? 1.0f : 0.0f;

    // ---- index math: F2I.RD (inputs non-negative), 32-bit offsets ----
    const int r = __float2int_rd(rc.x * (float)H);
    const int c = __float2int_rd(rc.y * (float)W);

    // all offsets < 2^26: keep address math in 32-bit
    const int base = b * (D * H * W) + r * W + c;
    float v0 = ebd[base + (2 * lane)     * (H * W)];
    float v1 = ebd[base + (2 * lane + 1) * (H * W)];
    unsigned long long vp = pack2(v0, v1);

    // ---- broadcast: local quarter via STS, 3 remote quarters via DSMEM ----
    {
        float* dst = &erow[chunk * KPC + kl][2 * lane];
        *(unsigned long long*)dst = vp;              // plain STS (own SMEM)
        unsigned vaddr = smem_u32(dst);
        #pragma unroll
        for (unsigned rk = 0; rk < CPB; rk++) {
            if (rk != (unsigned)chunk)
                st_cluster_b64(mapa_u32(vaddr, rk), vp);
        }
    }
    // cluster barrier: collective release/acquire for the DSMEM stores
    asm volatile("barrier.cluster.arrive.aligned;" ::: "memory");
    asm volatile("barrier.cluster.wait.aligned;"   ::: "memory");

    // ---- hoist own column j (packed f32x2) + own norm (register-local) ----
    const ulonglong2* row0 = (const ulonglong2*)erow[i0];  // hoisted row pointers
    const ulonglong2* row1 = (const ulonglong2*)erow[i1];

    unsigned long long ejp[D / 2];
    {
        const ulonglong2* myrow = (const ulonglong2*)erow[j];
        #pragma unroll
        for (int d4 = 0; d4 < D / 4; d4++) {
            ulonglong2 t = myrow[d4];
            ejp[2 * d4 + 0] = t.x;
            ejp[2 * d4 + 1] = t.y;
        }
    }
    float nj;
    {
        unsigned long long s01 = 0ull, s23 = 0ull;
        #pragma unroll
        for (int d4 = 0; d4 < D / 4; d4++) {
            s01 = ffma2(ejp[2 * d4 + 0], ejp[2 * d4 + 0], s01);
            s23 = ffma2(ejp[2 * d4 + 1], ejp[2 * d4 + 1], s23);
        }
        float2 a = unpack2(s01), bb = unpack2(s23);
        nj = (a.x + a.y) + (bb.x + bb.y);
    }

    // ---- pairwise loss: 2 i-rows per thread; i-norm computed inline ----
    float acc = 0.0f;
    #pragma unroll
    for (int ig = 0; ig < 2; ig++) {
        const ulonglong2* rowi = ig ? row1 : row0;             // warp-broadcast LDS.128
        const float ts = ig ? ts1 : ts0;
        unsigned long long s01 = 0ull, s23 = 0ull;             // dot(e_i, e_j)
        unsigned long long n01 = 0ull, n23 = 0ull;             // ||e_i||^2
        #pragma unroll
        for (int d4 = 0; d4 < D / 4; d4++) {
            ulonglong2 v = rowi[d4];
            s01 = ffma2(v.x, ejp[2 * d4 + 0], s01);
            s23 = ffma2(v.y, ejp[2 * d4 + 1], s23);
            n01 = ffma2(v.x, v.x, n01);
            n23 = ffma2(v.y, v.y, n23);
        }
        float2 a = unpack2(s01), bb = unpack2(s23);
        float s = (a.x + a.y) + (bb.x + bb.y);
        float2 na = unpack2(n01), nb = unpack2(n23);
        float ni = (na.x + na.y) + (nb.x + nb.y);

        // 2/(1+exp(t/D)): /D and log2e folded into one constant
        float t    = fmaf(-2.0f, s, ni + nj);
        float e    = exp2f(t * EXPO_C);
        float pred = __fdividef(2.0f, 1.0f + e);
        float dd   = pred - ts;
        acc = fmaf(dd, dd, acc);
    }

    // ---- CTA reduction: warp shuffle tree, then one warp over 16 leaders ----
    #pragma unroll
    for (int o = 16; o > 0; o >>= 1)
        acc += __shfl_down_sync(0xFFFFFFFFu, acc, o);
    if (lane == 0) swarp[tid >> 5] = acc;
    __syncthreads();

    if (tid < 32) {
        float v = (tid < THREADS / 32) ? swarp[tid] : 0.0f;
        #pragma unroll
        for (int o = 8; o > 0; o >>= 1)
            v += __shfl_down_sync(0xFFFFFFFFu, v, o);
        if (tid == 0) {
            unsigned long long q   = (unsigned long long)llrintf(v * QSCALE);
            unsigned long long val = q + CNT_ONE;
            unsigned long long old;
            asm volatile("atom.acq_rel.gpu.global.add.u64 %0, [%1], %2;"
                         : "=l"(old) : "l"(&g_acc), "l"(val) : "memory");
            if ((old >> 44) == GRID - 1) {
                unsigned long long total = (old + val) & QMASK;
                out[0] = (float)total * (1.0f / (QSCALE * (float)(K * K * B)));
                g_acc = 0ULL;             // reset for next graph replay
            }
        }
    }
}

extern "C" void kernel_launch(void* const* d_in, const int* in_sizes, int n_in,
                              void* d_out, int out_size)
{
    const float* ebd  = (const float*)d_in[0];   // [32,64,192,128] f32
    const float* kpts = (const float*)d_in[1];   // [32,64,2] f32
    const int*   tags = (const int*)d_in[2];     // [32,64] i32
    float* out = (float*)d_out;

    tagloss_fused_kernel<<<GRID, THREADS>>>(ebd, kpts, tags, out);
}